// round 14
// baseline (speedup 1.0000x reference)
#include <cuda_runtime.h>
#include <cuda_bf16.h>

// Problem constants: N=2,000,000 rows, P=64 features, C=100 classes.
#define PFEAT     64
#define NCLASS    100
#define NWARPS    16                  // class ownership = cls & 15
#define THREADS1  (NWARPS * 32)
#define GRID1     592                 // 148 SMs * 4 resident CTAs
#define BINS      (NCLASS * 32)       // [class][lane] float4 bins {sx, sy, ss, n}
#define SMEM1     (BINS * 16)         // 51,200 B -> dynamic smem (opt-in)

// Deterministic scratch (fixed-order reduction; no float atomics anywhere).
__device__ float4 g_part[(size_t)GRID1 * BINS];   // ~30.3 MB
__device__ double g_class[NCLASS];

__device__ __forceinline__ void l2_prefetch(const void* p) {
    asm volatile("prefetch.global.L2 [%0];" :: "l"(p));
}

// ---------------------------------------------------------------------------
// Kernel 1: warp w owns classes with (cls & 15) == w -> no atomics, and each
// lane only ever RMWs bin column [*, lane] -> no intra-warp aliasing.
// Unified float4 bin {sx, sy, ss, n}: ONE LDS.128/STS.128 RMW per row.
// L2 prefetch 2 windows ahead: the CTA consumes its x-chunk fully and
// sequentially, so prefetching converts the row LDG from DRAM-latency
// (~577 cyc) to L2-latency (~234 cyc).
// ---------------------------------------------------------------------------
__global__ __launch_bounds__(THREADS1, 4)
void k1_accumulate(const float2* __restrict__ x2,
                   const int* __restrict__ t, int N)   // t is int32
{
    extern __shared__ float4 bins[];   // [NCLASS][32]

    const int tid  = threadIdx.x;
    const int w    = tid >> 5;
    const int lane = tid & 31;

    for (int i = tid; i < BINS; i += THREADS1)
        bins[i] = make_float4(0.f, 0.f, 0.f, 0.f);
    __syncthreads();

    const int chunk = (N + GRID1 - 1) / GRID1;
    const int beg   = blockIdx.x * chunk;
    const int end   = min(N, beg + chunk);

    const char* xb = (const char*)x2;

    for (int base = beg; base < end; base += 32) {
        // Prefetch window base+64 into L2: 16 warps x 4 lanes cover the 8KB
        // x-window (64 lines of 128B); lane 4 fetches the t line.
        int pre = base + 64;
        if (pre < end) {
            if (lane < 4)
                l2_prefetch(xb + (size_t)pre * 256 + (w * 4 + lane) * 128);
            else if (lane == 4 && w == 0)
                l2_prefetch((const char*)t + (size_t)pre * 4);
        }

        int r   = base + lane;
        int cls = (r < end) ? t[r] : -1;
        bool own = (r < end) && ((cls & (NWARPS - 1)) == w);   // labels are 0..99
        unsigned m = __ballot_sync(0xffffffffu, own);

        while (m) {
            // Extract up to 2 owned rows, THEN issue both 256B loads (MLP=2).
            int b0 = __ffs(m) - 1;  m &= m - 1;
            int b1 = -1;
            if (m) { b1 = __ffs(m) - 1; m &= m - 1; }

            int c0 = __shfl_sync(0xffffffffu, cls, b0);
            int c1 = __shfl_sync(0xffffffffu, cls, b1 & 31);

            float2 v0, v1;
            v0 = x2[(size_t)(base + b0) * (PFEAT / 2) + lane];
            if (b1 >= 0) v1 = x2[(size_t)(base + b1) * (PFEAT / 2) + lane];

            {   // row b0 (always valid): single 16B RMW does s, ss, n
                int idx = c0 * 32 + lane;
                float4 a = bins[idx];
                a.x += v0.x;
                a.y += v0.y;
                a.z += v0.x * v0.x + v0.y * v0.y;
                a.w += 1.f;
                bins[idx] = a;
            }
            if (b1 >= 0) {
                int idx = c1 * 32 + lane;
                float4 a = bins[idx];
                a.x += v1.x;
                a.y += v1.y;
                a.z += v1.x * v1.x + v1.y * v1.y;
                a.w += 1.f;
                bins[idx] = a;
            }
        }
    }
    __syncthreads();

    const size_t off = (size_t)blockIdx.x * BINS;
    for (int i = tid; i < BINS; i += THREADS1)
        g_part[off + i] = bins[i];
}

// ---------------------------------------------------------------------------
// Kernel 2: one CTA (512 thr) per class; 16 warps split the 592 partials
// (37 serial iterations each), fixed-order combine in smem.
// ---------------------------------------------------------------------------
__global__ __launch_bounds__(512)
void k2_per_class()
{
    const int c    = blockIdx.x;
    const int tid  = threadIdx.x;
    const int w    = tid >> 5;
    const int lane = tid & 31;

    __shared__ float4 sa[512];

    float4 a = make_float4(0.f, 0.f, 0.f, 0.f);
    for (int b = w; b < GRID1; b += 16) {          // 512B coalesced per (b,warp)
        float4 p = g_part[(size_t)b * BINS + c * 32 + lane];
        a.x += p.x; a.y += p.y; a.z += p.z; a.w += p.w;
    }
    sa[tid] = a;
    __syncthreads();

    if (tid < 32) {
        float4 tot = sa[lane];
        #pragma unroll
        for (int j = 1; j < 16; j++) {
            float4 p = sa[j * 32 + lane];
            tot.x += p.x; tot.y += p.y; tot.z += p.z; tot.w += p.w;
        }
        // tot.w is n_c on every lane (each lane counted every row independently).
        double dA = (double)tot.x * tot.x + (double)tot.y * tot.y;  // s^2 partial
        double dB = (double)tot.z;                                   // ss partial
        #pragma unroll
        for (int o = 16; o > 0; o >>= 1) {
            dA += __shfl_xor_sync(0xffffffffu, dA, o);
            dB += __shfl_xor_sync(0xffffffffu, dB, o);
        }
        double dn = (double)tot.w;
        double contrib = (dB - dA / dn) / (dn - 1.0);
        if (lane == 0) g_class[c] = contrib;
    }
}

// ---------------------------------------------------------------------------
// Kernel 3: final deterministic reduction of the 100 class scalars.
// ---------------------------------------------------------------------------
__global__ void k3_final(float* __restrict__ out)
{
    if (threadIdx.x == 0) {
        double total = 0.0;
        for (int c = 0; c < NCLASS; c++) total += g_class[c];
        out[0] = (float)(total / (double)NCLASS);
    }
}

extern "C" void kernel_launch(void* const* d_in, const int* in_sizes, int n_in,
                              void* d_out, int out_size)
{
    const float2* x2  = (const float2*)d_in[0];
    const int*    t   = (const int*)d_in[1];          // int32 labels
    float*        out = (float*)d_out;
    const int N = in_sizes[0] / PFEAT;

    // Opt-in to >48KB dynamic shared memory (unconditional each call).
    cudaFuncSetAttribute(k1_accumulate, cudaFuncAttributeMaxDynamicSharedMemorySize, SMEM1);

    k1_accumulate<<<GRID1, THREADS1, SMEM1>>>(x2, t, N);
    k2_per_class<<<NCLASS, 512>>>();
    k3_final<<<1, 32>>>(out);
}

// round 16
// speedup vs baseline: 1.1831x; 1.1831x over previous
#include <cuda_runtime.h>
#include <cuda_bf16.h>
#include <cstdint>

// Problem constants: N=2,000,000 rows, P=64 features, C=100 classes.
#define PFEAT     64
#define NCLASS    100
#define NWARPS    16                   // class ownership = cls & 15
#define THREADS1  (NWARPS * 32)
#define GRID1     296                  // 148 SMs * 2 resident CTAs (smem-limited)
#define CHUNK     6784                 // ceil(2M/296) rounded up to multiple of 64
#define WROWS     64                   // staged window rows (N % 64 == 0 -> all full)
#define BINS      (NCLASS * 32)        // [class][lane] float4 bins {sx, sy, ss, n}
#define XBUF_B    (WROWS * 256)        // 16384 B per x buffer
#define SMEM1     (BINS * 16 + 2 * XBUF_B + 2 * WROWS * 4)   // 84,480 B

// Deterministic scratch (fixed-order reduction; no float atomics anywhere).
__device__ float4 g_part[(size_t)GRID1 * BINS];   // ~15.2 MB
__device__ double g_class[NCLASS];
__device__ int    g_done;                          // ticket; self-resets each run

__device__ __forceinline__ unsigned int smem_u32(const void* p) {
    return (unsigned int)__cvta_generic_to_shared(p);
}
__device__ __forceinline__ void cp_async16(unsigned int s, const void* g) {
    asm volatile("cp.async.cg.shared.global [%0], [%1], 16;" :: "r"(s), "l"(g));
}
__device__ __forceinline__ void cp_commit() {
    asm volatile("cp.async.commit_group;");
}

// ---------------------------------------------------------------------------
// Kernel 1: double-buffered cp.async staging of 64-row windows; ballot-owned
// binning out of smem. Warp w owns classes with (cls & 15) == w (no atomics;
// each lane only RMWs bin column [*, lane] -> no aliasing).
// ---------------------------------------------------------------------------
__global__ __launch_bounds__(THREADS1, 2)
void k1_accumulate(const float2* __restrict__ x2,
                   const int* __restrict__ t, int N)   // t is int32
{
    extern __shared__ unsigned char dyn[];
    float4* bins = reinterpret_cast<float4*>(dyn);                      // [NCLASS][32]
    float2* xbuf = reinterpret_cast<float2*>(dyn + BINS * 16);          // [2][WROWS][32]
    int*    tbuf = reinterpret_cast<int*>  (dyn + BINS * 16 + 2 * XBUF_B); // [2][WROWS]

    const int tid  = threadIdx.x;
    const int w    = tid >> 5;
    const int lane = tid & 31;

    for (int i = tid; i < BINS; i += THREADS1)
        bins[i] = make_float4(0.f, 0.f, 0.f, 0.f);
    __syncthreads();

    const int beg  = blockIdx.x * CHUNK;
    const int end  = min(N, beg + CHUNK);
    const int nwin = (end > beg) ? (end - beg) / WROWS : 0;   // all windows full

    const unsigned int xs_base = smem_u32(xbuf);
    const unsigned int ts_base = smem_u32(tbuf);
    const char*        gx      = (const char*)x2 + (size_t)beg * 256;
    const char*        gt      = (const char*)(t + beg);

    // Preload window 0 into buffer 0.
    if (nwin > 0) {
        for (int i = tid; i < XBUF_B / 16; i += THREADS1)
            cp_async16(xs_base + i * 16, gx + i * 16);
        if (tid < (WROWS * 4) / 16)
            cp_async16(ts_base + tid * 16, gt + tid * 16);
        cp_commit();
    }

    for (int win = 0; win < nwin; win++) {
        const int cur = win & 1;

        if (win + 1 < nwin) {   // stage next window into the other buffer
            const int          nxt = cur ^ 1;
            const char*        gxn = gx + (size_t)(win + 1) * XBUF_B;
            const char*        gtn = gt + (size_t)(win + 1) * WROWS * 4;
            const unsigned int sxn = xs_base + nxt * XBUF_B;
            const unsigned int stn = ts_base + nxt * WROWS * 4;
            for (int i = tid; i < XBUF_B / 16; i += THREADS1)
                cp_async16(sxn + i * 16, gxn + i * 16);
            if (tid < (WROWS * 4) / 16)
                cp_async16(stn + tid * 16, gtn + tid * 16);
            cp_commit();
            asm volatile("cp.async.wait_group 1;");
        } else {
            asm volatile("cp.async.wait_group 0;");
        }
        __syncthreads();          // window `win` staged & visible to all warps

        const float2* xs = xbuf + cur * (WROWS * 32);
        const int*    ts = tbuf + cur * WROWS;

        #pragma unroll
        for (int sub = 0; sub < 2; sub++) {
            const int lb  = sub * 32;
            int  cls = ts[lb + lane];                     // labels are 0..99
            bool own = ((cls & (NWARPS - 1)) == w);
            unsigned m = __ballot_sync(0xffffffffu, own);

            while (m) {
                int b0 = __ffs(m) - 1;  m &= m - 1;
                int b1 = -1;
                if (m) { b1 = __ffs(m) - 1; m &= m - 1; }

                int c0 = __shfl_sync(0xffffffffu, cls, b0);
                int c1 = __shfl_sync(0xffffffffu, cls, b1 & 31);

                float2 v0, v1;
                v0 = xs[(lb + b0) * 32 + lane];           // LDS.64, conflict-free
                if (b1 >= 0) v1 = xs[(lb + b1) * 32 + lane];

                {   // row b0: single 16B RMW does s, ss, n
                    int idx = c0 * 32 + lane;
                    float4 a = bins[idx];
                    a.x += v0.x;
                    a.y += v0.y;
                    a.z += v0.x * v0.x + v0.y * v0.y;
                    a.w += 1.f;
                    bins[idx] = a;
                }
                if (b1 >= 0) {
                    int idx = c1 * 32 + lane;
                    float4 a = bins[idx];
                    a.x += v1.x;
                    a.y += v1.y;
                    a.z += v1.x * v1.x + v1.y * v1.y;
                    a.w += 1.f;
                    bins[idx] = a;
                }
            }
        }
        __syncthreads();          // all warps done with buf[cur] before overwrite
    }

    const size_t off = (size_t)blockIdx.x * BINS;
    for (int i = tid; i < BINS; i += THREADS1)
        g_part[off + i] = bins[i];
}

// ---------------------------------------------------------------------------
// Kernel 2: one CTA (512 thr) per class; fixed-order reduction of partials.
// Last CTA (integer-atomic ticket) performs the deterministic final sum.
// ---------------------------------------------------------------------------
__global__ __launch_bounds__(512)
void k2_per_class(float* __restrict__ out)
{
    const int c    = blockIdx.x;
    const int tid  = threadIdx.x;
    const int w    = tid >> 5;
    const int lane = tid & 31;

    __shared__ float4 sa[512];

    float4 a = make_float4(0.f, 0.f, 0.f, 0.f);
    for (int b = w; b < GRID1; b += 16) {          // 512B coalesced per (b,warp)
        float4 p = g_part[(size_t)b * BINS + c * 32 + lane];
        a.x += p.x; a.y += p.y; a.z += p.z; a.w += p.w;
    }
    sa[tid] = a;
    __syncthreads();

    if (tid < 32) {
        float4 tot = sa[lane];
        #pragma unroll
        for (int j = 1; j < 16; j++) {
            float4 p = sa[j * 32 + lane];
            tot.x += p.x; tot.y += p.y; tot.z += p.z; tot.w += p.w;
        }
        // tot.w is n_c on every lane (each lane counted every row).
        double dA = (double)tot.x * tot.x + (double)tot.y * tot.y;  // s^2 partial
        double dB = (double)tot.z;                                   // ss partial
        #pragma unroll
        for (int o = 16; o > 0; o >>= 1) {
            dA += __shfl_xor_sync(0xffffffffu, dA, o);
            dB += __shfl_xor_sync(0xffffffffu, dB, o);
        }
        if (lane == 0) {
            double dn = tot.w;
            g_class[c] = (dB - dA / dn) / (dn - 1.0);
            __threadfence();
            int tk = atomicAdd(&g_done, 1);
            if (tk == gridDim.x - 1) {             // last CTA: fixed-order final
                double total = 0.0;
                for (int i = 0; i < NCLASS; i++) total += g_class[i];
                out[0] = (float)(total / (double)NCLASS);
                g_done = 0;                        // self-reset for graph replay
            }
        }
    }
}

extern "C" void kernel_launch(void* const* d_in, const int* in_sizes, int n_in,
                              void* d_out, int out_size)
{
    const float2* x2  = (const float2*)d_in[0];
    const int*    t   = (const int*)d_in[1];          // int32 labels
    float*        out = (float*)d_out;
    const int N = in_sizes[0] / PFEAT;

    // Opt-in to >48KB dynamic shared memory (unconditional each call).
    cudaFuncSetAttribute(k1_accumulate, cudaFuncAttributeMaxDynamicSharedMemorySize, SMEM1);

    k1_accumulate<<<GRID1, THREADS1, SMEM1>>>(x2, t, N);
    k2_per_class<<<NCLASS, 512>>>(out);
}